// round 8
// baseline (speedup 1.0000x reference)
#include <cuda_runtime.h>
#include <cuda_bf16.h>
#include <cstdint>

// ---------------- problem constants ----------------
#define NN 100000
#define EE 3200000
#define GG 128
#define DIN 128
#define DH  256
#define DOUT 64
#define BN_EPS 1e-3f
#define NB_SCAN ((NN + 1023) / 1024)   // 98

// ---------------- device scratch (static, no allocs) ----------------
// invariant: g_deg_in/g_deg_out are ZERO at entry of every call
// (zero-initialized at module load; re-zeroed in k_scanC each call)
__device__ int      g_deg_in [NN];
__device__ int      g_deg_out[NN];
__device__ float    g_norm_src[NN];
__device__ float    g_norm_dst[NN];
__device__ int      g_off[NN + 1];
__device__ int      g_cursor[NN];
__device__ int      g_bsum[NB_SCAN];
__device__ int      g_csr_src[EE];
__device__ float    g_agg[(size_t)NN * DH];
__device__ float    g_h1 [(size_t)NN * DH];
__device__ float    g_h2 [(size_t)NN * DH];
__device__ uint32_t g_xb [(size_t)NN * DH / 2];   // bf16x2 staging (reused per layer)
__device__ float    g_W0f[DIN * DH];
__device__ float    g_Wf [2 * DH * DH];
__device__ float    g_bf [3 * DH];
__device__ float    g_pool[GG * DH];
__device__ int      g_gcount[GG];

// ---------------- helpers ----------------
__device__ __forceinline__ uint32_t f2tf(float f) {
    uint32_t u;
    asm("cvt.rna.tf32.f32 %0, %1;" : "=r"(u) : "f"(f));
    return u;
}
__device__ __forceinline__ float bflo(uint32_t u) { return __uint_as_float(u << 16); }
__device__ __forceinline__ float bfhi(uint32_t u) { return __uint_as_float(u & 0xffff0000u); }

// ---------------- preprocessing ----------------

// degrees via atomics; also zero pool accumulators for this call
__global__ void k_deg(const int* __restrict__ src, const int* __restrict__ dst) {
    int e = blockIdx.x * 256 + threadIdx.x;
    if (e < EE) {
        atomicAdd(&g_deg_out[src[e]], 1);
        atomicAdd(&g_deg_in [dst[e]], 1);
    }
    if (e < GG * DH) g_pool[e] = 0.f;
    if (e < GG) g_gcount[e] = 0;
}

// per-block exclusive scan of deg_in; block totals to g_bsum; also compute norms
__global__ void __launch_bounds__(1024) k_scanA() {
    __shared__ int sh[1024];
    const int t = threadIdx.x;
    const int i = blockIdx.x * 1024 + t;
    int v = (i < NN) ? g_deg_in[i] : 0;
    sh[t] = v;
    __syncthreads();
#pragma unroll
    for (int d = 1; d < 1024; d <<= 1) {
        int u = (t >= d) ? sh[t - d] : 0;
        __syncthreads();
        sh[t] += u;
        __syncthreads();
    }
    if (i < NN) {
        g_off[i] = sh[t] - v;
        g_norm_dst[i] = rsqrtf(fmaxf((float)v, 1.f));
        g_norm_src[i] = rsqrtf(fmaxf((float)g_deg_out[i], 1.f));
    }
    if (t == 1023) g_bsum[blockIdx.x] = sh[t];
}

// add block offsets (block-sum prefix computed in-shared), mirror to cursor,
// close array, and re-zero degree arrays for the next call
__global__ void __launch_bounds__(1024) k_scanC() {
    __shared__ int sb[128];
    const int t = threadIdx.x;
    if (t < 128) sb[t] = (t < NB_SCAN) ? g_bsum[t] : 0;
    __syncthreads();
#pragma unroll
    for (int d = 1; d < 128; d <<= 1) {
        int u = 0;
        if (t < 128 && t >= d) u = sb[t - d];
        __syncthreads();
        if (t < 128) sb[t] += u;
        __syncthreads();
    }
    const int boff = (blockIdx.x == 0) ? 0 : sb[blockIdx.x - 1];
    const int i = blockIdx.x * 1024 + t;
    if (i < NN) {
        int o = g_off[i] + boff;
        g_off[i] = o;
        g_cursor[i] = o;
        g_deg_in[i] = 0;
        g_deg_out[i] = 0;
    }
    if (i == 0) g_off[NN] = EE;
}

__global__ void k_csr(const int* __restrict__ src, const int* __restrict__ dst) {
    int e = blockIdx.x * 256 + threadIdx.x;
    if (e < EE) {
        int pos = atomicAdd(&g_cursor[dst[e]], 1);
        g_csr_src[pos] = src[e];
    }
}

// convert input h (fp32) to packed bf16x2 staging buffer
__global__ void __launch_bounds__(256) k_cvt(const float* __restrict__ h) {
    size_t i = (size_t)blockIdx.x * 256 + threadIdx.x;
    if (i < (size_t)NN * DIN / 2) {
        float2 f = ((const float2*)h)[i];
        __nv_bfloat162 b = __floats2bfloat162_rn(f.x, f.y);
        g_xb[i] = *reinterpret_cast<uint32_t*>(&b);
    }
}

// fold BN scale into weights and biases
__global__ void k_fold(const float* __restrict__ W0, const float* __restrict__ b0,
                       const float* __restrict__ W,  const float* __restrict__ b,
                       const float* __restrict__ gamma, const float* __restrict__ beta,
                       const float* __restrict__ mean,  const float* __restrict__ var) {
    int idx = blockIdx.x * 256 + threadIdx.x;
    if (idx < 2 * DH * DH) {
        int l = idx >> 16;
        int j = idx & (DH - 1);
        float a = gamma[(l + 1) * DH + j] * rsqrtf(var[(l + 1) * DH + j] + BN_EPS);
        g_Wf[idx] = W[idx] * a;
    }
    if (idx < DIN * DH) {
        int j = idx & (DH - 1);
        float a = gamma[j] * rsqrtf(var[j] + BN_EPS);
        g_W0f[idx] = W0[idx] * a;
    }
    if (idx < 3 * DH) {
        int l = idx >> 8;
        int j = idx & (DH - 1);
        float a = gamma[idx] * rsqrtf(var[idx] + BN_EPS);
        float bl = (l == 0) ? b0[j] : b[(l - 1) * DH + j];
        g_bf[idx] = bl * a + beta[idx] - mean[idx] * a;
    }
}

// ---------------- aggregation (bf16 gather SpMM) ----------------
// agg[n,:] = sum_{e in CSR(n)} x[src_e,:] * norm_src[src_e]
template <int D>
__global__ void __launch_bounds__(256) k_agg_bf(float* __restrict__ agg) {
    constexpr int V = D / 8;      // uint4 lanes per row: 32 (D=256) / 16 (D=128)
    constexpr int G = 256 / V;    // edge groups per block: 8 / 16
    __shared__ int   sh_s[64];
    __shared__ float sh_ns[64];
    __shared__ float red[256 * 8];
    const int n = blockIdx.x;
    const int tid = threadIdx.x;
    const int g = tid / V;
    const int v = tid % V;
    const int beg = g_off[n], end = g_off[n + 1];
    const uint4* __restrict__ xb4 = (const uint4*)g_xb;

    float acc[8];
#pragma unroll
    for (int q = 0; q < 8; q++) acc[q] = 0.f;

    for (int base = beg; base < end; base += 64) {
        int m = end - base; if (m > 64) m = 64;
        if (tid < m) {
            int s = g_csr_src[base + tid];
            sh_s[tid]  = s;
            sh_ns[tid] = g_norm_src[s];
        }
        __syncthreads();
        for (int j = g; j < m; j += G) {
            const uint4 u = xb4[(size_t)sh_s[j] * (D / 8) + v];
            const float w = sh_ns[j];
            acc[0] = fmaf(bflo(u.x), w, acc[0]);
            acc[1] = fmaf(bfhi(u.x), w, acc[1]);
            acc[2] = fmaf(bflo(u.y), w, acc[2]);
            acc[3] = fmaf(bfhi(u.y), w, acc[3]);
            acc[4] = fmaf(bflo(u.z), w, acc[4]);
            acc[5] = fmaf(bfhi(u.z), w, acc[5]);
            acc[6] = fmaf(bflo(u.w), w, acc[6]);
            acc[7] = fmaf(bfhi(u.w), w, acc[7]);
        }
        __syncthreads();
    }

#pragma unroll
    for (int q = 0; q < 8; q++) red[tid * 8 + q] = acc[q];
    __syncthreads();
#pragma unroll
    for (int half = G / 2; half > 0; half >>= 1) {
        if (g < half) {
#pragma unroll
            for (int q = 0; q < 8; q++) {
                acc[q] += red[((g + half) * V + v) * 8 + q];
                red[tid * 8 + q] = acc[q];
            }
        }
        __syncthreads();
    }
    if (g == 0) {
        float4 a0 = make_float4(acc[0], acc[1], acc[2], acc[3]);
        float4 a1 = make_float4(acc[4], acc[5], acc[6], acc[7]);
        *(float4*)(agg + (size_t)n * D + v * 8)     = a0;
        *(float4*)(agg + (size_t)n * D + v * 8 + 4) = a1;
    }
}

// ---------------- TF32 tensor-core GEMM ----------------
// C[N x 256] = A[N x K] @ B[K x 256], epilogue:
// v = relu(acc * norm_dst[row] + biasf[col]); v += res[row,col] (optional);
// C <- v (fp32); bh <- v (packed bf16, optional)
#define AST 136
__global__ void __launch_bounds__(256) k_gemm_tf32(const float* __restrict__ A, int K,
                                                   const float* __restrict__ B,
                                                   const float* __restrict__ biasf,
                                                   const float* __restrict__ res,
                                                   float* __restrict__ C,
                                                   __nv_bfloat16* __restrict__ bh) {
    __shared__ uint32_t As[16 * AST];
    __shared__ uint32_t Bs[16 * AST];
    const int tid  = threadIdx.x;
    const int lane = tid & 31;
    const int warp = tid >> 5;
    const int wm = warp & 3;
    const int wn = warp >> 2;
    const int gq  = lane >> 2;
    const int tig = lane & 3;
    const int rowBase = blockIdx.y * 128;
    const int colBase = blockIdx.x * 128;

    const int r0 = tid >> 2;
    const int kq = tid & 3;
    int ar0 = rowBase + r0;       if (ar0 > NN - 1) ar0 = NN - 1;
    int ar1 = rowBase + r0 + 64;  if (ar1 > NN - 1) ar1 = NN - 1;
    const int kr = tid >> 5;
    const int n4 = (tid & 31) * 4;

    float acc[2][8][4];
#pragma unroll
    for (int mt = 0; mt < 2; mt++)
#pragma unroll
        for (int nt = 0; nt < 8; nt++)
#pragma unroll
            for (int q = 0; q < 4; q++) acc[mt][nt][q] = 0.f;

    for (int k0 = 0; k0 < K; k0 += 16) {
        float4 av0 = *(const float4*)(A + (size_t)ar0 * K + k0 + kq * 4);
        float4 av1 = *(const float4*)(A + (size_t)ar1 * K + k0 + kq * 4);
        As[(kq * 4 + 0) * AST + r0] = f2tf(av0.x);
        As[(kq * 4 + 1) * AST + r0] = f2tf(av0.y);
        As[(kq * 4 + 2) * AST + r0] = f2tf(av0.z);
        As[(kq * 4 + 3) * AST + r0] = f2tf(av0.w);
        As[(kq * 4 + 0) * AST + r0 + 64] = f2tf(av1.x);
        As[(kq * 4 + 1) * AST + r0 + 64] = f2tf(av1.y);
        As[(kq * 4 + 2) * AST + r0 + 64] = f2tf(av1.z);
        As[(kq * 4 + 3) * AST + r0 + 64] = f2tf(av1.w);
        float4 bv0 = *(const float4*)(B + (size_t)(k0 + kr)     * DH + colBase + n4);
        float4 bv1 = *(const float4*)(B + (size_t)(k0 + kr + 8) * DH + colBase + n4);
        uint4 bu0 = make_uint4(f2tf(bv0.x), f2tf(bv0.y), f2tf(bv0.z), f2tf(bv0.w));
        uint4 bu1 = make_uint4(f2tf(bv1.x), f2tf(bv1.y), f2tf(bv1.z), f2tf(bv1.w));
        *(uint4*)(&Bs[kr       * AST + n4]) = bu0;
        *(uint4*)(&Bs[(kr + 8) * AST + n4]) = bu1;
        __syncthreads();

#pragma unroll
        for (int kk = 0; kk < 16; kk += 8) {
            uint32_t af[2][4];
#pragma unroll
            for (int mt = 0; mt < 2; mt++) {
                int mb = wm * 32 + mt * 16 + gq;
                af[mt][0] = As[(kk + tig)     * AST + mb];
                af[mt][1] = As[(kk + tig)     * AST + mb + 8];
                af[mt][2] = As[(kk + tig + 4) * AST + mb];
                af[mt][3] = As[(kk + tig + 4) * AST + mb + 8];
            }
#pragma unroll
            for (int nt = 0; nt < 8; nt++) {
                int nb = wn * 64 + nt * 8 + gq;
                uint32_t b0 = Bs[(kk + tig)     * AST + nb];
                uint32_t b1 = Bs[(kk + tig + 4) * AST + nb];
#pragma unroll
                for (int mt = 0; mt < 2; mt++) {
                    asm volatile(
                        "mma.sync.aligned.m16n8k8.row.col.f32.tf32.tf32.f32 "
                        "{%0,%1,%2,%3}, {%4,%5,%6,%7}, {%8,%9}, {%0,%1,%2,%3};\n"
                        : "+f"(acc[mt][nt][0]), "+f"(acc[mt][nt][1]),
                          "+f"(acc[mt][nt][2]), "+f"(acc[mt][nt][3])
                        : "r"(af[mt][0]), "r"(af[mt][1]), "r"(af[mt][2]), "r"(af[mt][3]),
                          "r"(b0), "r"(b1));
                }
            }
        }
        __syncthreads();
    }

#pragma unroll
    for (int mt = 0; mt < 2; mt++) {
#pragma unroll
        for (int half = 0; half < 2; half++) {
            int r = rowBase + wm * 32 + mt * 16 + gq + half * 8;
            if (r < NN) {
                float nd = g_norm_dst[r];
#pragma unroll
                for (int nt = 0; nt < 8; nt++) {
                    int c = colBase + wn * 64 + nt * 8 + 2 * tig;
                    float v0 = fmaxf(fmaf(acc[mt][nt][half * 2 + 0], nd, biasf[c]),     0.f);
                    float v1 = fmaxf(fmaf(acc[mt][nt][half * 2 + 1], nd, biasf[c + 1]), 0.f);
                    if (res) {
                        float2 rv = *(const float2*)(res + (size_t)r * DH + c);
                        v0 += rv.x; v1 += rv.y;
                    }
                    float2 o; o.x = v0; o.y = v1;
                    *(float2*)(C + (size_t)r * DH + c) = o;
                    if (bh) {
                        __nv_bfloat162 b2 = __floats2bfloat162_rn(v0, v1);
                        *reinterpret_cast<__nv_bfloat162*>(bh + (size_t)r * DH + c) = b2;
                    }
                }
            }
        }
    }
}

// ---------------- pooling + head ----------------

__global__ void __launch_bounds__(256) k_pool(const float* __restrict__ h,
                                              const int* __restrict__ gid) {
    const int f = threadIdx.x;
    int n0 = blockIdx.x * 64;
    int n1 = n0 + 64; if (n1 > NN) n1 = NN;
    if (n0 >= NN) return;
    float acc = 0.f;
    int cnt = 0;
    int cur = gid[n0];
    for (int n = n0; n < n1; n++) {
        int g = gid[n];
        if (g != cur) {
            atomicAdd(&g_pool[cur * DH + f], acc);
            if (f == 0) atomicAdd(&g_gcount[cur], cnt);
            acc = 0.f; cnt = 0; cur = g;
        }
        acc += h[(size_t)n * DH + f];
        cnt++;
    }
    atomicAdd(&g_pool[cur * DH + f], acc);
    if (f == 0) atomicAdd(&g_gcount[cur], cnt);
}

__global__ void __launch_bounds__(64) k_head(const float* __restrict__ Wp,
                                             const float* __restrict__ bp,
                                             float* __restrict__ out) {
    const int g = blockIdx.x;
    const int j = threadIdx.x;
    __shared__ float sp[DH];
    float inv = 1.f / fmaxf((float)g_gcount[g], 1.f);
    for (int k = j; k < DH; k += 64) sp[k] = g_pool[g * DH + k] * inv;
    __syncthreads();
    float s = 0.f;
    for (int k = 0; k < DH; k++)
        s = fmaf(sp[k], Wp[k * DOUT + j], s);
    out[g * DOUT + j] = s + bp[j];
}

// ---------------- launch ----------------
extern "C" void kernel_launch(void* const* d_in, const int* in_sizes, int n_in,
                              void* d_out, int out_size) {
    const float* h    = (const float*)d_in[0];
    const float* W0   = (const float*)d_in[1];
    const float* b0   = (const float*)d_in[2];
    const float* W    = (const float*)d_in[3];
    const float* b    = (const float*)d_in[4];
    const float* bng  = (const float*)d_in[5];
    const float* bnb  = (const float*)d_in[6];
    const float* bnm  = (const float*)d_in[7];
    const float* bnv  = (const float*)d_in[8];
    const float* Wp   = (const float*)d_in[9];
    const float* bp   = (const float*)d_in[10];
    const int*   src  = (const int*)d_in[11];
    const int*   dst  = (const int*)d_in[12];
    const int*   gid  = (const int*)d_in[13];
    float* out = (float*)d_out;

    float *agg, *h1, *h2, *W0f, *Wf, *bf;
    __nv_bfloat16* xb;
    cudaGetSymbolAddress((void**)&agg, g_agg);
    cudaGetSymbolAddress((void**)&h1,  g_h1);
    cudaGetSymbolAddress((void**)&h2,  g_h2);
    cudaGetSymbolAddress((void**)&xb,  g_xb);
    cudaGetSymbolAddress((void**)&W0f, g_W0f);
    cudaGetSymbolAddress((void**)&Wf,  g_Wf);
    cudaGetSymbolAddress((void**)&bf,  g_bf);

    const int nb_e = (EE + 255) / 256;

    // preprocessing: 4th launch (k_csr) is the one ncu captures
    k_deg  <<<nb_e, 256>>>(src, dst);
    k_scanA<<<NB_SCAN, 1024>>>();
    k_scanC<<<NB_SCAN, 1024>>>();
    k_csr  <<<nb_e, 256>>>(src, dst);
    k_cvt  <<<(NN * DIN / 2 + 255) / 256, 256>>>(h);
    k_fold <<<(2 * DH * DH + 255) / 256, 256>>>(W0, b0, W, b, bng, bnb, bnm, bnv);

    dim3 gemmGrid(DH / 128, (NN + 127) / 128);

    // layer 0: agg over bf16(h) in D=128, GEMM K=128, no residual; bf16 out -> xb
    k_agg_bf<DIN><<<NN, 256>>>(agg);
    k_gemm_tf32<<<gemmGrid, 256>>>(agg, DIN, W0f, bf, nullptr, h1, xb);

    // layer 1: agg over bf16(h1), GEMM K=256, residual h1; bf16 out -> xb
    k_agg_bf<DH><<<NN, 256>>>(agg);
    k_gemm_tf32<<<gemmGrid, 256>>>(agg, DH, Wf, bf + DH, h1, h2, xb);

    // layer 2: agg over bf16(h2), residual h2, write into h1; no bf16 out
    k_agg_bf<DH><<<NN, 256>>>(agg);
    k_gemm_tf32<<<gemmGrid, 256>>>(agg, DH, Wf + DH * DH, bf + 2 * DH, h2, h1, nullptr);

    // pooling + head
    k_pool<<<(NN + 63) / 64, 256>>>(h1, gid);
    k_head<<<GG, DOUT>>>(Wp, bp, out);
}

// round 9
// speedup vs baseline: 2.3739x; 2.3739x over previous
#include <cuda_runtime.h>
#include <cuda_bf16.h>
#include <cstdint>

// ---------------- problem constants ----------------
#define NN 100000
#define EE 3200000
#define GG 128
#define DIN 128
#define DH  256
#define DOUT 64
#define BN_EPS 1e-3f
#define NB_SCAN ((NN + 1023) / 1024)   // 98

// ---------------- device scratch (static, no allocs) ----------------
// invariant: g_deg_in/g_deg_out are ZERO at entry of every call
__device__ int      g_deg_in [NN];
__device__ int      g_deg_out[NN];
__device__ float    g_norm_src[NN];
__device__ float    g_norm_dst[NN];
__device__ int      g_off[NN + 1];
__device__ int      g_cursor[NN];
__device__ int      g_bsum[NB_SCAN];
__device__ int2     g_csr_sn[EE];                 // (src, norm_src bits)
__device__ float    g_agg[(size_t)NN * DH];
__device__ float    g_h1 [(size_t)NN * DH];
__device__ float    g_h2 [(size_t)NN * DH];
__device__ uint32_t g_xb [(size_t)NN * DH / 2];   // bf16x2 staging (reused per layer)
__device__ float    g_W0f[DIN * DH];
__device__ float    g_Wf [2 * DH * DH];
__device__ float    g_bf [3 * DH];
__device__ float    g_pool[GG * DH];
__device__ int      g_gcount[GG];

// ---------------- helpers ----------------
__device__ __forceinline__ uint32_t f2tf(float f) {
    uint32_t u;
    asm("cvt.rna.tf32.f32 %0, %1;" : "=r"(u) : "f"(f));
    return u;
}
__device__ __forceinline__ float bflo(uint32_t u) { return __uint_as_float(u << 16); }
__device__ __forceinline__ float bfhi(uint32_t u) { return __uint_as_float(u & 0xffff0000u); }

// ---------------- preprocessing ----------------

__global__ void k_deg(const int* __restrict__ src, const int* __restrict__ dst) {
    int e = blockIdx.x * 256 + threadIdx.x;
    if (e < EE) {
        atomicAdd(&g_deg_out[src[e]], 1);
        atomicAdd(&g_deg_in [dst[e]], 1);
    }
    if (e < GG * DH) g_pool[e] = 0.f;
    if (e < GG) g_gcount[e] = 0;
}

__global__ void __launch_bounds__(1024) k_scanA() {
    __shared__ int sh[1024];
    const int t = threadIdx.x;
    const int i = blockIdx.x * 1024 + t;
    int v = (i < NN) ? g_deg_in[i] : 0;
    sh[t] = v;
    __syncthreads();
#pragma unroll
    for (int d = 1; d < 1024; d <<= 1) {
        int u = (t >= d) ? sh[t - d] : 0;
        __syncthreads();
        sh[t] += u;
        __syncthreads();
    }
    if (i < NN) {
        g_off[i] = sh[t] - v;
        g_norm_dst[i] = rsqrtf(fmaxf((float)v, 1.f));
        g_norm_src[i] = rsqrtf(fmaxf((float)g_deg_out[i], 1.f));
    }
    if (t == 1023) g_bsum[blockIdx.x] = sh[t];
}

__global__ void __launch_bounds__(1024) k_scanC() {
    __shared__ int sb[128];
    const int t = threadIdx.x;
    if (t < 128) sb[t] = (t < NB_SCAN) ? g_bsum[t] : 0;
    __syncthreads();
#pragma unroll
    for (int d = 1; d < 128; d <<= 1) {
        int u = 0;
        if (t < 128 && t >= d) u = sb[t - d];
        __syncthreads();
        if (t < 128) sb[t] += u;
        __syncthreads();
    }
    const int boff = (blockIdx.x == 0) ? 0 : sb[blockIdx.x - 1];
    const int i = blockIdx.x * 1024 + t;
    if (i < NN) {
        int o = g_off[i] + boff;
        g_off[i] = o;
        g_cursor[i] = o;
        g_deg_in[i] = 0;
        g_deg_out[i] = 0;
    }
    if (i == 0) g_off[NN] = EE;
}

// scatter edges into dst-CSR; pre-gather norm_src so the agg inner loop
// needs no random norm lookups
__global__ void k_csr(const int* __restrict__ src, const int* __restrict__ dst) {
    int e = blockIdx.x * 256 + threadIdx.x;
    if (e < EE) {
        int s = src[e];
        int pos = atomicAdd(&g_cursor[dst[e]], 1);
        g_csr_sn[pos] = make_int2(s, __float_as_int(g_norm_src[s]));
    }
}

__global__ void __launch_bounds__(256) k_cvt(const float* __restrict__ h) {
    size_t i = (size_t)blockIdx.x * 256 + threadIdx.x;
    if (i < (size_t)NN * DIN / 2) {
        float2 f = ((const float2*)h)[i];
        __nv_bfloat162 b = __floats2bfloat162_rn(f.x, f.y);
        g_xb[i] = *reinterpret_cast<uint32_t*>(&b);
    }
}

__global__ void k_fold(const float* __restrict__ W0, const float* __restrict__ b0,
                       const float* __restrict__ W,  const float* __restrict__ b,
                       const float* __restrict__ gamma, const float* __restrict__ beta,
                       const float* __restrict__ mean,  const float* __restrict__ var) {
    int idx = blockIdx.x * 256 + threadIdx.x;
    if (idx < 2 * DH * DH) {
        int l = idx >> 16;
        int j = idx & (DH - 1);
        float a = gamma[(l + 1) * DH + j] * rsqrtf(var[(l + 1) * DH + j] + BN_EPS);
        g_Wf[idx] = W[idx] * a;
    }
    if (idx < DIN * DH) {
        int j = idx & (DH - 1);
        float a = gamma[j] * rsqrtf(var[j] + BN_EPS);
        g_W0f[idx] = W0[idx] * a;
    }
    if (idx < 3 * DH) {
        int l = idx >> 8;
        int j = idx & (DH - 1);
        float a = gamma[idx] * rsqrtf(var[idx] + BN_EPS);
        float bl = (l == 0) ? b0[j] : b[(l - 1) * DH + j];
        g_bf[idx] = bl * a + beta[idx] - mean[idx] * a;
    }
}

// ---------------- aggregation: warp-per-node bf16 gather ----------------
// agg[n,:] = sum_{e in CSR(n)} bf16(x)[src_e,:] * norm_src[src_e]
// One warp per node. Lane l owns a 16B (D=256) / 8B (D=128) slice of the row.
// Edge (src, norm) pairs loaded coalesced (int2) and shfl-broadcast.
// No shared memory, no __syncthreads, fp32 accumulation in registers.
template <int D>
__global__ void __launch_bounds__(256) k_aggw(float* __restrict__ agg) {
    const int w = blockIdx.x * 8 + (threadIdx.x >> 5);
    if (w >= NN) return;
    const int lane = threadIdx.x & 31;
    const int beg = g_off[w], end = g_off[w + 1];
    constexpr int VALS = D / 32;          // 8 (D=256) or 4 (D=128)
    float acc[VALS];
#pragma unroll
    for (int q = 0; q < VALS; q++) acc[q] = 0.f;

    for (int base = beg; base < end; base += 32) {
        const int m = min(32, end - base);
        const int2 esn = g_csr_sn[base + (lane < m ? lane : 0)];
#pragma unroll 4
        for (int j = 0; j < m; j++) {
            const int   sj = __shfl_sync(0xffffffffu, esn.x, j);
            const float nj = __uint_as_float(__shfl_sync(0xffffffffu, (unsigned)esn.y, j));
            if (D == 256) {
                const uint4 u = __ldg(((const uint4*)g_xb) + (size_t)sj * 32 + lane);
                acc[0] = fmaf(bflo(u.x), nj, acc[0]);
                acc[1] = fmaf(bfhi(u.x), nj, acc[1]);
                acc[2] = fmaf(bflo(u.y), nj, acc[2]);
                acc[3] = fmaf(bfhi(u.y), nj, acc[3]);
                acc[4] = fmaf(bflo(u.z), nj, acc[4]);
                acc[5] = fmaf(bfhi(u.z), nj, acc[5]);
                acc[6] = fmaf(bflo(u.w), nj, acc[6]);
                acc[7] = fmaf(bfhi(u.w), nj, acc[7]);
            } else {
                const uint2 u = __ldg(((const uint2*)g_xb) + (size_t)sj * 32 + lane);
                acc[0] = fmaf(bflo(u.x), nj, acc[0]);
                acc[1] = fmaf(bfhi(u.x), nj, acc[1]);
                acc[2] = fmaf(bflo(u.y), nj, acc[2]);
                acc[3] = fmaf(bfhi(u.y), nj, acc[3]);
            }
        }
    }

    if (D == 256) {
        *(float4*)(agg + (size_t)w * D + lane * 8)     = make_float4(acc[0], acc[1], acc[2], acc[3]);
        *(float4*)(agg + (size_t)w * D + lane * 8 + 4) = make_float4(acc[VALS - 4], acc[VALS - 3], acc[VALS - 2], acc[VALS - 1]);
    } else {
        *(float4*)(agg + (size_t)w * D + lane * 4)     = make_float4(acc[0], acc[1], acc[2], acc[3]);
    }
}

// ---------------- TF32 tensor-core GEMM ----------------
// C[N x 256] = A[N x K] @ B[K x 256]; epilogue:
// v = relu(acc * norm_dst[row] + biasf[col]); v += res (optional);
// C <- v (fp32); bh <- v (packed bf16, optional)
#define AST 140
__global__ void __launch_bounds__(256) k_gemm_tf32(const float* __restrict__ A, int K,
                                                   const float* __restrict__ B,
                                                   const float* __restrict__ biasf,
                                                   const float* __restrict__ res,
                                                   float* __restrict__ C,
                                                   __nv_bfloat16* __restrict__ bh) {
    __shared__ uint32_t As[16 * AST];
    __shared__ uint32_t Bs[16 * AST];
    const int tid  = threadIdx.x;
    const int lane = tid & 31;
    const int warp = tid >> 5;
    const int wm = warp & 3;
    const int wn = warp >> 2;
    const int gq  = lane >> 2;
    const int tig = lane & 3;
    const int rowBase = blockIdx.y * 128;
    const int colBase = blockIdx.x * 128;

    const int r0 = tid >> 2;
    const int kq = tid & 3;
    int ar0 = rowBase + r0;       if (ar0 > NN - 1) ar0 = NN - 1;
    int ar1 = rowBase + r0 + 64;  if (ar1 > NN - 1) ar1 = NN - 1;
    const int kr = tid >> 5;
    const int n4 = (tid & 31) * 4;

    float acc[2][8][4];
#pragma unroll
    for (int mt = 0; mt < 2; mt++)
#pragma unroll
        for (int nt = 0; nt < 8; nt++)
#pragma unroll
            for (int q = 0; q < 4; q++) acc[mt][nt][q] = 0.f;

    for (int k0 = 0; k0 < K; k0 += 16) {
        float4 av0 = *(const float4*)(A + (size_t)ar0 * K + k0 + kq * 4);
        float4 av1 = *(const float4*)(A + (size_t)ar1 * K + k0 + kq * 4);
        As[(kq * 4 + 0) * AST + r0] = f2tf(av0.x);
        As[(kq * 4 + 1) * AST + r0] = f2tf(av0.y);
        As[(kq * 4 + 2) * AST + r0] = f2tf(av0.z);
        As[(kq * 4 + 3) * AST + r0] = f2tf(av0.w);
        As[(kq * 4 + 0) * AST + r0 + 64] = f2tf(av1.x);
        As[(kq * 4 + 1) * AST + r0 + 64] = f2tf(av1.y);
        As[(kq * 4 + 2) * AST + r0 + 64] = f2tf(av1.z);
        As[(kq * 4 + 3) * AST + r0 + 64] = f2tf(av1.w);
        float4 bv0 = *(const float4*)(B + (size_t)(k0 + kr)     * DH + colBase + n4);
        float4 bv1 = *(const float4*)(B + (size_t)(k0 + kr + 8) * DH + colBase + n4);
        uint4 bu0 = make_uint4(f2tf(bv0.x), f2tf(bv0.y), f2tf(bv0.z), f2tf(bv0.w));
        uint4 bu1 = make_uint4(f2tf(bv1.x), f2tf(bv1.y), f2tf(bv1.z), f2tf(bv1.w));
        *(uint4*)(&Bs[kr       * AST + n4]) = bu0;
        *(uint4*)(&Bs[(kr + 8) * AST + n4]) = bu1;
        __syncthreads();

#pragma unroll
        for (int kk = 0; kk < 16; kk += 8) {
            uint32_t af[2][4];
#pragma unroll
            for (int mt = 0; mt < 2; mt++) {
                int mb = wm * 32 + mt * 16 + gq;
                af[mt][0] = As[(kk + tig)     * AST + mb];
                af[mt][1] = As[(kk + tig)     * AST + mb + 8];
                af[mt][2] = As[(kk + tig + 4) * AST + mb];
                af[mt][3] = As[(kk + tig + 4) * AST + mb + 8];
            }
#pragma unroll
            for (int nt = 0; nt < 8; nt++) {
                int nb = wn * 64 + nt * 8 + gq;
                uint32_t b0 = Bs[(kk + tig)     * AST + nb];
                uint32_t b1 = Bs[(kk + tig + 4) * AST + nb];
#pragma unroll
                for (int mt = 0; mt < 2; mt++) {
                    asm volatile(
                        "mma.sync.aligned.m16n8k8.row.col.f32.tf32.tf32.f32 "
                        "{%0,%1,%2,%3}, {%4,%5,%6,%7}, {%8,%9}, {%0,%1,%2,%3};\n"
                        : "+f"(acc[mt][nt][0]), "+f"(acc[mt][nt][1]),
                          "+f"(acc[mt][nt][2]), "+f"(acc[mt][nt][3])
                        : "r"(af[mt][0]), "r"(af[mt][1]), "r"(af[mt][2]), "r"(af[mt][3]),
                          "r"(b0), "r"(b1));
                }
            }
        }
        __syncthreads();
    }

#pragma unroll
    for (int mt = 0; mt < 2; mt++) {
#pragma unroll
        for (int half = 0; half < 2; half++) {
            int r = rowBase + wm * 32 + mt * 16 + gq + half * 8;
            if (r < NN) {
                float nd = g_norm_dst[r];
#pragma unroll
                for (int nt = 0; nt < 8; nt++) {
                    int c = colBase + wn * 64 + nt * 8 + 2 * tig;
                    float v0 = fmaxf(fmaf(acc[mt][nt][half * 2 + 0], nd, biasf[c]),     0.f);
                    float v1 = fmaxf(fmaf(acc[mt][nt][half * 2 + 1], nd, biasf[c + 1]), 0.f);
                    if (res) {
                        float2 rv = *(const float2*)(res + (size_t)r * DH + c);
                        v0 += rv.x; v1 += rv.y;
                    }
                    float2 o; o.x = v0; o.y = v1;
                    *(float2*)(C + (size_t)r * DH + c) = o;
                    if (bh) {
                        __nv_bfloat162 b2 = __floats2bfloat162_rn(v0, v1);
                        *reinterpret_cast<__nv_bfloat162*>(bh + (size_t)r * DH + c) = b2;
                    }
                }
            }
        }
    }
}

// ---------------- pooling + head ----------------

__global__ void __launch_bounds__(256) k_pool(const float* __restrict__ h,
                                              const int* __restrict__ gid) {
    const int f = threadIdx.x;
    int n0 = blockIdx.x * 64;
    int n1 = n0 + 64; if (n1 > NN) n1 = NN;
    if (n0 >= NN) return;
    float acc = 0.f;
    int cnt = 0;
    int cur = gid[n0];
    for (int n = n0; n < n1; n++) {
        int g = gid[n];
        if (g != cur) {
            atomicAdd(&g_pool[cur * DH + f], acc);
            if (f == 0) atomicAdd(&g_gcount[cur], cnt);
            acc = 0.f; cnt = 0; cur = g;
        }
        acc += h[(size_t)n * DH + f];
        cnt++;
    }
    atomicAdd(&g_pool[cur * DH + f], acc);
    if (f == 0) atomicAdd(&g_gcount[cur], cnt);
}

__global__ void __launch_bounds__(64) k_head(const float* __restrict__ Wp,
                                             const float* __restrict__ bp,
                                             float* __restrict__ out) {
    const int g = blockIdx.x;
    const int j = threadIdx.x;
    __shared__ float sp[DH];
    float inv = 1.f / fmaxf((float)g_gcount[g], 1.f);
    for (int k = j; k < DH; k += 64) sp[k] = g_pool[g * DH + k] * inv;
    __syncthreads();
    float s = 0.f;
    for (int k = 0; k < DH; k++)
        s = fmaf(sp[k], Wp[k * DOUT + j], s);
    out[g * DOUT + j] = s + bp[j];
}

// ---------------- launch ----------------
extern "C" void kernel_launch(void* const* d_in, const int* in_sizes, int n_in,
                              void* d_out, int out_size) {
    const float* h    = (const float*)d_in[0];
    const float* W0   = (const float*)d_in[1];
    const float* b0   = (const float*)d_in[2];
    const float* W    = (const float*)d_in[3];
    const float* b    = (const float*)d_in[4];
    const float* bng  = (const float*)d_in[5];
    const float* bnb  = (const float*)d_in[6];
    const float* bnm  = (const float*)d_in[7];
    const float* bnv  = (const float*)d_in[8];
    const float* Wp   = (const float*)d_in[9];
    const float* bp   = (const float*)d_in[10];
    const int*   src  = (const int*)d_in[11];
    const int*   dst  = (const int*)d_in[12];
    const int*   gid  = (const int*)d_in[13];
    float* out = (float*)d_out;

    float *agg, *h1, *h2, *W0f, *Wf, *bf;
    __nv_bfloat16* xb;
    cudaGetSymbolAddress((void**)&agg, g_agg);
    cudaGetSymbolAddress((void**)&h1,  g_h1);
    cudaGetSymbolAddress((void**)&h2,  g_h2);
    cudaGetSymbolAddress((void**)&xb,  g_xb);
    cudaGetSymbolAddress((void**)&W0f, g_W0f);
    cudaGetSymbolAddress((void**)&Wf,  g_Wf);
    cudaGetSymbolAddress((void**)&bf,  g_bf);

    const int nb_e = (EE + 255) / 256;

    k_deg  <<<nb_e, 256>>>(src, dst);
    k_scanA<<<NB_SCAN, 1024>>>();
    k_scanC<<<NB_SCAN, 1024>>>();
    k_csr  <<<nb_e, 256>>>(src, dst);
    k_cvt  <<<(NN * DIN / 2 + 255) / 256, 256>>>(h);
    k_fold <<<(2 * DH * DH + 255) / 256, 256>>>(W0, b0, W, b, bng, bnb, bnm, bnv);

    dim3 gemmGrid(DH / 128, (NN + 127) / 128);
    const int aggGrid = (NN + 7) / 8;

    // layer 0: agg over bf16(h) in D=128, GEMM K=128, no residual; bf16 out -> xb
    k_aggw<DIN><<<aggGrid, 256>>>(agg);
    k_gemm_tf32<<<gemmGrid, 256>>>(agg, DIN, W0f, bf, nullptr, h1, xb);

    // layer 1: agg over bf16(h1), GEMM K=256, residual h1; bf16 out -> xb
    k_aggw<DH><<<aggGrid, 256>>>(agg);
    k_gemm_tf32<<<gemmGrid, 256>>>(agg, DH, Wf, bf + DH, h1, h2, xb);

    // layer 2: agg over bf16(h2), residual h2, write into h1; no bf16 out
    k_aggw<DH><<<aggGrid, 256>>>(agg);
    k_gemm_tf32<<<gemmGrid, 256>>>(agg, DH, Wf + DH * DH, bf + 2 * DH, h2, h1, nullptr);

    // pooling + head
    k_pool<<<(NN + 63) / 64, 256>>>(h1, gid);
    k_head<<<GG, DOUT>>>(Wp, bp, out);
}

// round 11
// speedup vs baseline: 3.2872x; 1.3847x over previous
#include <cuda_runtime.h>
#include <cuda_bf16.h>
#include <cstdint>

// ---------------- problem constants ----------------
#define NN 100000
#define EE 3200000
#define GG 128
#define DIN 128
#define DH  256
#define DOUT 64
#define BN_EPS 1e-3f
#define NB_SCAN ((NN + 1023) / 1024)   // 98

// ---------------- device scratch (static, no allocs) ----------------
// invariant: g_deg_in/g_deg_out are ZERO at entry of every call
__device__ int      g_deg_in [NN];
__device__ int      g_deg_out[NN];
__device__ float    g_norm_src[NN];
__device__ float    g_norm_dst[NN];
__device__ int      g_off[NN + 1];
__device__ int      g_cursor[NN];
__device__ int      g_bsum[NB_SCAN];
__device__ int2     g_csr_sn[EE];                    // (src, norm_src bits)
__device__ uint32_t g_hx [(size_t)NN * DIN / 2];     // bf16(h) input
__device__ uint32_t g_ab [(size_t)NN * DH / 2];      // agg output (bf16)
__device__ uint32_t g_b0 [(size_t)NN * DH / 2];      // layer0 out (bf16)
__device__ uint32_t g_b1 [(size_t)NN * DH / 2];      // layer1 out (bf16)
__device__ uint32_t g_b2 [(size_t)NN * DH / 2];      // layer2 out (bf16)
__device__ __nv_bfloat16 g_W0b[DH * DIN];            // [n][k] bf16
__device__ __nv_bfloat16 g_Wb [2 * DH * DH];         // [l][n][k] bf16
__device__ float    g_bf [3 * DH];
__device__ float    g_pool[GG * DH];
__device__ int      g_gcount[GG];

// ---------------- helpers ----------------
__device__ __forceinline__ float bflo(uint32_t u) { return __uint_as_float(u << 16); }
__device__ __forceinline__ float bfhi(uint32_t u) { return __uint_as_float(u & 0xffff0000u); }

// ---------------- preprocessing ----------------

__global__ void k_deg(const int* __restrict__ src, const int* __restrict__ dst) {
    int e = blockIdx.x * 256 + threadIdx.x;
    if (e < EE) {
        atomicAdd(&g_deg_out[src[e]], 1);
        atomicAdd(&g_deg_in [dst[e]], 1);
    }
    if (e < GG * DH) g_pool[e] = 0.f;
    if (e < GG) g_gcount[e] = 0;
}

__global__ void __launch_bounds__(1024) k_scanA() {
    __shared__ int sh[1024];
    const int t = threadIdx.x;
    const int i = blockIdx.x * 1024 + t;
    int v = (i < NN) ? g_deg_in[i] : 0;
    sh[t] = v;
    __syncthreads();
#pragma unroll
    for (int d = 1; d < 1024; d <<= 1) {
        int u = (t >= d) ? sh[t - d] : 0;
        __syncthreads();
        sh[t] += u;
        __syncthreads();
    }
    if (i < NN) {
        g_off[i] = sh[t] - v;
        g_norm_dst[i] = rsqrtf(fmaxf((float)v, 1.f));
        g_norm_src[i] = rsqrtf(fmaxf((float)g_deg_out[i], 1.f));
    }
    if (t == 1023) g_bsum[blockIdx.x] = sh[t];
}

__global__ void __launch_bounds__(1024) k_scanC() {
    __shared__ int sb[128];
    const int t = threadIdx.x;
    if (t < 128) sb[t] = (t < NB_SCAN) ? g_bsum[t] : 0;
    __syncthreads();
#pragma unroll
    for (int d = 1; d < 128; d <<= 1) {
        int u = 0;
        if (t < 128 && t >= d) u = sb[t - d];
        __syncthreads();
        if (t < 128) sb[t] += u;
        __syncthreads();
    }
    const int boff = (blockIdx.x == 0) ? 0 : sb[blockIdx.x - 1];
    const int i = blockIdx.x * 1024 + t;
    if (i < NN) {
        int o = g_off[i] + boff;
        g_off[i] = o;
        g_cursor[i] = o;
        g_deg_in[i] = 0;
        g_deg_out[i] = 0;
    }
    if (i == 0) g_off[NN] = EE;
}

__global__ void k_csr(const int* __restrict__ src, const int* __restrict__ dst) {
    int e = blockIdx.x * 256 + threadIdx.x;
    if (e < EE) {
        int s = src[e];
        int pos = atomicAdd(&g_cursor[dst[e]], 1);
        g_csr_sn[pos] = make_int2(s, __float_as_int(g_norm_src[s]));
    }
}

__global__ void __launch_bounds__(256) k_cvt(const float* __restrict__ h) {
    size_t i = (size_t)blockIdx.x * 256 + threadIdx.x;
    if (i < (size_t)NN * DIN / 2) {
        float2 f = ((const float2*)h)[i];
        __nv_bfloat162 b = __floats2bfloat162_rn(f.x, f.y);
        g_hx[i] = *reinterpret_cast<uint32_t*>(&b);
    }
}

// fold BN scale into weights (bf16, transposed to [n][k]) and biases (fp32)
__global__ void k_fold(const float* __restrict__ W0, const float* __restrict__ b0,
                       const float* __restrict__ W,  const float* __restrict__ b,
                       const float* __restrict__ gamma, const float* __restrict__ beta,
                       const float* __restrict__ mean,  const float* __restrict__ var) {
    int idx = blockIdx.x * 256 + threadIdx.x;
    if (idx < 2 * DH * DH) {
        int l = idx >> 16;
        int r = idx & (DH * DH - 1);
        int n = r / DH;                 // output col
        int k = r % DH;                 // input row
        float a = gamma[(l + 1) * DH + n] * rsqrtf(var[(l + 1) * DH + n] + BN_EPS);
        g_Wb[idx] = __float2bfloat16(W[l * DH * DH + k * DH + n] * a);
    }
    if (idx < DH * DIN) {
        int n = idx / DIN;
        int k = idx % DIN;
        float a = gamma[n] * rsqrtf(var[n] + BN_EPS);
        g_W0b[idx] = __float2bfloat16(W0[k * DH + n] * a);
    }
    if (idx < 3 * DH) {
        int l = idx >> 8;
        int j = idx & (DH - 1);
        float a = gamma[idx] * rsqrtf(var[idx] + BN_EPS);
        float bl = (l == 0) ? b0[j] : b[(l - 1) * DH + j];
        g_bf[idx] = bl * a + beta[idx] - mean[idx] * a;
    }
}

// ---------------- aggregation: warp-per-node bf16 gather, bf16 output ----------------
template <int D>
__global__ void __launch_bounds__(256) k_aggw(const uint32_t* __restrict__ xin,
                                              uint32_t* __restrict__ aggb) {
    const int w = blockIdx.x * 8 + (threadIdx.x >> 5);
    if (w >= NN) return;
    const int lane = threadIdx.x & 31;
    const int beg = g_off[w], end = g_off[w + 1];
    constexpr int VALS = D / 32;          // 8 (D=256) or 4 (D=128)
    float acc[VALS];
#pragma unroll
    for (int q = 0; q < VALS; q++) acc[q] = 0.f;

    for (int base = beg; base < end; base += 32) {
        const int m = min(32, end - base);
        const int2 esn = g_csr_sn[base + (lane < m ? lane : 0)];
#pragma unroll 4
        for (int j = 0; j < m; j++) {
            const int   sj = __shfl_sync(0xffffffffu, esn.x, j);
            const float nj = __uint_as_float(__shfl_sync(0xffffffffu, (unsigned)esn.y, j));
            if (D == 256) {
                const uint4 u = __ldg(((const uint4*)xin) + (size_t)sj * 32 + lane);
                acc[0] = fmaf(bflo(u.x), nj, acc[0]);
                acc[1] = fmaf(bfhi(u.x), nj, acc[1]);
                acc[2] = fmaf(bflo(u.y), nj, acc[2]);
                acc[3] = fmaf(bfhi(u.y), nj, acc[3]);
                acc[4] = fmaf(bflo(u.z), nj, acc[4]);
                acc[5] = fmaf(bfhi(u.z), nj, acc[5]);
                acc[6] = fmaf(bflo(u.w), nj, acc[6]);
                acc[7] = fmaf(bfhi(u.w), nj, acc[7]);
            } else {
                const uint2 u = __ldg(((const uint2*)xin) + (size_t)sj * 32 + lane);
                acc[0] = fmaf(bflo(u.x), nj, acc[0]);
                acc[1] = fmaf(bfhi(u.x), nj, acc[1]);
                acc[2] = fmaf(bflo(u.y), nj, acc[2]);
                acc[3] = fmaf(bfhi(u.y), nj, acc[3]);
            }
        }
    }

    if (D == 256) {
        __nv_bfloat162 p0 = __floats2bfloat162_rn(acc[0], acc[1]);
        __nv_bfloat162 p1 = __floats2bfloat162_rn(acc[2], acc[3]);
        __nv_bfloat162 p2 = __floats2bfloat162_rn(acc[4], acc[5]);
        __nv_bfloat162 p3 = __floats2bfloat162_rn(acc[6], acc[7]);
        uint4 o;
        o.x = *reinterpret_cast<uint32_t*>(&p0);
        o.y = *reinterpret_cast<uint32_t*>(&p1);
        o.z = *reinterpret_cast<uint32_t*>(&p2);
        o.w = *reinterpret_cast<uint32_t*>(&p3);
        ((uint4*)aggb)[(size_t)w * 32 + lane] = o;
    } else {
        __nv_bfloat162 p0 = __floats2bfloat162_rn(acc[0], acc[1]);
        __nv_bfloat162 p1 = __floats2bfloat162_rn(acc[2], acc[3]);
        uint2 o;
        o.x = *reinterpret_cast<uint32_t*>(&p0);
        o.y = *reinterpret_cast<uint32_t*>(&p1);
        ((uint2*)aggb)[(size_t)w * 32 + lane] = o;
    }
}

// ---------------- BF16 tensor-core GEMM ----------------
// C[N x 256] (bf16) = A[N x K] (bf16) @ Bw^T, Bw stored [n][k] bf16.
// epilogue: v = relu(acc * norm_dst[row] + biasf[col]); v += res (bf16, optional)
#define ASTR 40   // bf16 elements per smem row (32 data + 8 pad) -> conflict-free frags
__global__ void __launch_bounds__(256) k_gemm_bf(const __nv_bfloat16* __restrict__ A, int K,
                                                 const __nv_bfloat16* __restrict__ Bw,
                                                 const float* __restrict__ biasf,
                                                 const __nv_bfloat16* __restrict__ res,
                                                 __nv_bfloat16* __restrict__ C) {
    __shared__ __nv_bfloat16 As[128 * ASTR];
    __shared__ __nv_bfloat16 Bs[128 * ASTR];
    const int tid  = threadIdx.x;
    const int lane = tid & 31;
    const int warp = tid >> 5;
    const int wm = warp & 3;      // 4 warps x 32 rows
    const int wn = warp >> 2;     // 2 warps x 64 cols
    const int gq  = lane >> 2;    // 0..7
    const int tig = lane & 3;     // 0..3
    const int rowBase = blockIdx.y * 128;
    const int colBase = blockIdx.x * 128;

    // staging: slot s in [0,512): row=s>>2, q=s&3 -> 8 bf16 at [row][q*8]
    const int srow = tid >> 2;
    const int sq   = tid & 3;
    int ar0 = rowBase + srow;        if (ar0 > NN - 1) ar0 = NN - 1;
    int ar1 = rowBase + srow + 64;   if (ar1 > NN - 1) ar1 = NN - 1;

    float acc[2][8][4];
#pragma unroll
    for (int mt = 0; mt < 2; mt++)
#pragma unroll
        for (int nt = 0; nt < 8; nt++)
#pragma unroll
            for (int q = 0; q < 4; q++) acc[mt][nt][q] = 0.f;

    for (int k0 = 0; k0 < K; k0 += 32) {
        // A: 128 rows x 32 k (bf16), 2 slots per thread
        {
            uint4 v0 = *(const uint4*)(A + (size_t)ar0 * K + k0 + sq * 8);
            uint4 v1 = *(const uint4*)(A + (size_t)ar1 * K + k0 + sq * 8);
            *(uint4*)(&As[srow * ASTR + sq * 8])        = v0;
            *(uint4*)(&As[(srow + 64) * ASTR + sq * 8]) = v1;
        }
        // B: 128 n-rows x 32 k (bf16), layout already [n][k]
        {
            uint4 b0 = *(const uint4*)(Bw + (size_t)(colBase + srow) * K + k0 + sq * 8);
            uint4 b1 = *(const uint4*)(Bw + (size_t)(colBase + srow + 64) * K + k0 + sq * 8);
            *(uint4*)(&Bs[srow * ASTR + sq * 8])        = b0;
            *(uint4*)(&Bs[(srow + 64) * ASTR + sq * 8]) = b1;
        }
        __syncthreads();

#pragma unroll
        for (int kk = 0; kk < 32; kk += 16) {
            uint32_t af[2][4];
#pragma unroll
            for (int mt = 0; mt < 2; mt++) {
                int m = wm * 32 + mt * 16 + gq;
                af[mt][0] = *(const uint32_t*)(&As[m * ASTR + kk + 2 * tig]);
                af[mt][1] = *(const uint32_t*)(&As[(m + 8) * ASTR + kk + 2 * tig]);
                af[mt][2] = *(const uint32_t*)(&As[m * ASTR + kk + 2 * tig + 8]);
                af[mt][3] = *(const uint32_t*)(&As[(m + 8) * ASTR + kk + 2 * tig + 8]);
            }
#pragma unroll
            for (int nt = 0; nt < 8; nt++) {
                int n = wn * 64 + nt * 8 + gq;
                uint32_t b0 = *(const uint32_t*)(&Bs[n * ASTR + kk + 2 * tig]);
                uint32_t b1 = *(const uint32_t*)(&Bs[n * ASTR + kk + 2 * tig + 8]);
#pragma unroll
                for (int mt = 0; mt < 2; mt++) {
                    asm volatile(
                        "mma.sync.aligned.m16n8k16.row.col.f32.bf16.bf16.f32 "
                        "{%0,%1,%2,%3}, {%4,%5,%6,%7}, {%8,%9}, {%0,%1,%2,%3};\n"
                        : "+f"(acc[mt][nt][0]), "+f"(acc[mt][nt][1]),
                          "+f"(acc[mt][nt][2]), "+f"(acc[mt][nt][3])
                        : "r"(af[mt][0]), "r"(af[mt][1]), "r"(af[mt][2]), "r"(af[mt][3]),
                          "r"(b0), "r"(b1));
                }
            }
        }
        __syncthreads();
    }

    // epilogue: acc c0,c1 -> row gq, cols 2tig..; c2,c3 -> row gq+8
#pragma unroll
    for (int mt = 0; mt < 2; mt++) {
#pragma unroll
        for (int half = 0; half < 2; half++) {
            int r = rowBase + wm * 32 + mt * 16 + half * 8 + gq;
            if (r < NN) {
                float nd = g_norm_dst[r];
#pragma unroll
                for (int nt = 0; nt < 8; nt++) {
                    int c = colBase + wn * 64 + nt * 8 + 2 * tig;
                    float v0 = fmaxf(fmaf(acc[mt][nt][half * 2 + 0], nd, biasf[c]),     0.f);
                    float v1 = fmaxf(fmaf(acc[mt][nt][half * 2 + 1], nd, biasf[c + 1]), 0.f);
                    if (res) {
                        __nv_bfloat162 rv = *reinterpret_cast<const __nv_bfloat162*>(
                            res + (size_t)r * DH + c);
                        v0 += __bfloat162float(rv.x);
                        v1 += __bfloat162float(rv.y);
                    }
                    __nv_bfloat162 o = __floats2bfloat162_rn(v0, v1);
                    *reinterpret_cast<__nv_bfloat162*>(C + (size_t)r * DH + c) = o;
                }
            }
        }
    }
}

// ---------------- pooling + head ----------------

__global__ void __launch_bounds__(256) k_pool(const __nv_bfloat16* __restrict__ h,
                                              const int* __restrict__ gid) {
    const int f = threadIdx.x;
    int n0 = blockIdx.x * 64;
    int n1 = n0 + 64; if (n1 > NN) n1 = NN;
    if (n0 >= NN) return;
    float acc = 0.f;
    int cnt = 0;
    int cur = gid[n0];
    for (int n = n0; n < n1; n++) {
        int g = gid[n];
        if (g != cur) {
            atomicAdd(&g_pool[cur * DH + f], acc);
            if (f == 0) atomicAdd(&g_gcount[cur], cnt);
            acc = 0.f; cnt = 0; cur = g;
        }
        acc += __bfloat162float(h[(size_t)n * DH + f]);
        cnt++;
    }
    atomicAdd(&g_pool[cur * DH + f], acc);
    if (f == 0) atomicAdd(&g_gcount[cur], cnt);
}

__global__ void __launch_bounds__(64) k_head(const float* __restrict__ Wp,
                                             const float* __restrict__ bp,
                                             float* __restrict__ out) {
    const int g = blockIdx.x;
    const int j = threadIdx.x;
    __shared__ float sp[DH];
    float inv = 1.f / fmaxf((float)g_gcount[g], 1.f);
    for (int k = j; k < DH; k += 64) sp[k] = g_pool[g * DH + k] * inv;
    __syncthreads();
    float s = 0.f;
    for (int k = 0; k < DH; k++)
        s = fmaf(sp[k], Wp[k * DOUT + j], s);
    out[g * DOUT + j] = s + bp[j];
}

// ---------------- launch ----------------
extern "C" void kernel_launch(void* const* d_in, const int* in_sizes, int n_in,
                              void* d_out, int out_size) {
    const float* h    = (const float*)d_in[0];
    const float* W0   = (const float*)d_in[1];
    const float* b0   = (const float*)d_in[2];
    const float* W    = (const float*)d_in[3];
    const float* b    = (const float*)d_in[4];
    const float* bng  = (const float*)d_in[5];
    const float* bnb  = (const float*)d_in[6];
    const float* bnm  = (const float*)d_in[7];
    const float* bnv  = (const float*)d_in[8];
    const float* Wp   = (const float*)d_in[9];
    const float* bp   = (const float*)d_in[10];
    const int*   src  = (const int*)d_in[11];
    const int*   dst  = (const int*)d_in[12];
    const int*   gid  = (const int*)d_in[13];
    float* out = (float*)d_out;

    uint32_t *hx, *ab, *b0b, *b1b, *b2b;
    __nv_bfloat16 *W0b, *Wb;
    float *bf;
    cudaGetSymbolAddress((void**)&hx,  g_hx);
    cudaGetSymbolAddress((void**)&ab,  g_ab);
    cudaGetSymbolAddress((void**)&b0b, g_b0);
    cudaGetSymbolAddress((void**)&b1b, g_b1);
    cudaGetSymbolAddress((void**)&b2b, g_b2);
    cudaGetSymbolAddress((void**)&W0b, g_W0b);
    cudaGetSymbolAddress((void**)&Wb,  g_Wb);
    cudaGetSymbolAddress((void**)&bf,  g_bf);

    const int nb_e = (EE + 255) / 256;

    k_deg  <<<nb_e, 256>>>(src, dst);
    k_scanA<<<NB_SCAN, 1024>>>();
    k_scanC<<<NB_SCAN, 1024>>>();
    k_csr  <<<nb_e, 256>>>(src, dst);
    k_cvt  <<<(NN * DIN / 2 + 255) / 256, 256>>>(h);
    k_fold <<<(2 * DH * DH + 255) / 256, 256>>>(W0, b0, W, b, bng, bnb, bnm, bnv);

    dim3 gemmGrid(DH / 128, (NN + 127) / 128);
    const int aggGrid = (NN + 7) / 8;

    // layer 0: agg over bf16(h) D=128; GEMM K=128; no residual -> b0 (bf16)
    k_aggw<DIN><<<aggGrid, 256>>>(hx, ab);
    k_gemm_bf<<<gemmGrid, 256>>>((const __nv_bfloat16*)ab, DIN, W0b, bf,
                                 nullptr, (__nv_bfloat16*)b0b);

    // layer 1: agg over b0; GEMM K=256; residual b0 -> b1
    k_aggw<DH><<<aggGrid, 256>>>(b0b, ab);
    k_gemm_bf<<<gemmGrid, 256>>>((const __nv_bfloat16*)ab, DH, Wb, bf + DH,
                                 (const __nv_bfloat16*)b0b, (__nv_bfloat16*)b1b);

    // layer 2: agg over b1; residual b1 -> b2
    k_aggw<DH><<<aggGrid, 256>>>(b1b, ab);
    k_gemm_bf<<<gemmGrid, 256>>>((const __nv_bfloat16*)ab, DH, Wb + DH * DH, bf + 2 * DH,
                                 (const __nv_bfloat16*)b1b, (__nv_bfloat16*)b2b);

    // pooling + head
    k_pool<<<(NN + 63) / 64, 256>>>((const __nv_bfloat16*)b2b, gid);
    k_head<<<GG, DOUT>>>(Wp, bp, out);
}